// round 16
// baseline (speedup 1.0000x reference)
#include <cuda_runtime.h>
#include <cuda_fp16.h>
#include <math.h>
#include <stdint.h>

// ---------------------------------------------------------------------------
// Scratch (device globals — no allocation allowed)
// ---------------------------------------------------------------------------
__device__ __half         g_w1h[64 * 48];      // conv1 weights fp16 [co][k=ky*8+kx]
__device__ float          g_b1[64];
__device__ __half         g_w2h[25 * 64 * 64]; // conv2 weights fp16 [pos][co][ci]
__device__ float          g_b2[64];
__device__ float          g_w3[10 * 1024];
__device__ float          g_b3[10];
__device__ __half         g_p1h[(size_t)2048 * 144 * 64];  // pool1 fp16, ch-last
__device__ float          g_pool2[(size_t)2048 * 1024];
__device__ float          g_smax1[2048];
__device__ float          g_max2[64 * 2048];   // transposed: [c][n]
__device__ float          g_stat2[64];
__device__ int            g_ctr1;              // stat1 arrivals   (reset by k_conv1)
__device__ int            g_ctr_w2;            // stat2 arrivals   (reset by k_conv2)
__device__ int            g_ctr_lin;           // stat3 arrivals   (reset by k_conv1)

// ---------------------------------------------------------------------------
// Helpers
// ---------------------------------------------------------------------------
__device__ __forceinline__ float warp_max(float v) {
    #pragma unroll
    for (int o = 16; o; o >>= 1) v = fmaxf(v, __shfl_xor_sync(0xFFFFFFFFu, v, o));
    return v;
}
__device__ __forceinline__ float warp_sum(float v) {
    #pragma unroll
    for (int o = 16; o; o >>= 1) v += __shfl_xor_sync(0xFFFFFFFFu, v, o);
    return v;
}
__device__ __forceinline__ float scinol_p(float p0, float S2, float G, float eta,
                                          float M, bool cond) {
    float denom = sqrtf(S2 + M * M);
    float theta = fminf(fmaxf(G / denom, -1.0f), 1.0f);
    float upd = cond ? theta / (2.0f * denom) * eta : 0.0f;
    return p0 + upd;
}

// fp16 HMMA: D(16x8) += A(16x16)*B(16x8), fp32 accum. sm_80+.
__device__ __forceinline__ void mma16816h(float* d, const uint32_t* a, const uint32_t* b) {
    asm volatile(
        "mma.sync.aligned.m16n8k16.row.col.f32.f16.f16.f32 "
        "{%0,%1,%2,%3}, {%4,%5,%6,%7}, {%8,%9}, {%0,%1,%2,%3};"
        : "+f"(d[0]), "+f"(d[1]), "+f"(d[2]), "+f"(d[3])
        : "r"(a[0]), "r"(a[1]), "r"(a[2]), "r"(a[3]), "r"(b[0]), "r"(b[1]));
}

__device__ __forceinline__ void spin_until(int* ctr, int target) {
    // caller: one thread spins, then __syncthreads() outside
    while (*(volatile int*)ctr < target) { }
    __threadfence();
}

// ---------------------------------------------------------------------------
// k_stat1 (fused): per-sample max of |x|; last block finalizes mean and
// builds conv1 weights (fp16, [co][48]) + bias.
// ---------------------------------------------------------------------------
__global__ void k_stat1(const float* __restrict__ x,
                        const float* __restrict__ w0, const float* __restrict__ wS2,
                        const float* __restrict__ wG, const float* __restrict__ weta,
                        const float* __restrict__ wM,
                        const float* __restrict__ b0, const float* __restrict__ bS2,
                        const float* __restrict__ bG, const float* __restrict__ beta) {
    int n = blockIdx.x;
    int tid = threadIdx.x;
    const float* xp = x + (size_t)n * 784;
    float m = 0.0f;
    for (int i = tid; i < 784; i += 256) m = fmaxf(m, fabsf(xp[i]));
    __shared__ float s[8];
    __shared__ int sold;
    m = warp_max(m);
    if ((tid & 31) == 0) s[tid >> 5] = m;
    __syncthreads();
    if (tid < 32) {
        float v = (tid < 8) ? s[tid] : 0.0f;
        v = warp_max(v);
        if (tid == 0) {
            g_smax1[n] = v;
            __threadfence();
            sold = atomicAdd(&g_ctr1, 1);
        }
    }
    __syncthreads();
    if (sold != 2047) return;

    // final block: all g_smax1 visible (every producer fenced before arriving)
    __threadfence();
    __shared__ float sm[8];
    __shared__ float s_stat;
    float sum = 0.0f;
    for (int i = tid; i < 2048; i += 256) sum += g_smax1[i];
    sum = warp_sum(sum);
    if ((tid & 31) == 0) sm[tid >> 5] = sum;
    __syncthreads();
    if (tid < 32) {
        float v = (tid < 8) ? sm[tid] : 0.0f;
        v = warp_sum(v);
        if (tid == 0) s_stat = v * (1.0f / 2048.0f);
    }
    __syncthreads();
    float M = fmaxf(s_stat, wM[0]);

    for (int p = tid; p < 3072; p += 256) {
        int co = p / 48, k = p - co * 48;
        int ky = k >> 3, kx = k & 7;
        float w = 0.0f;
        if (ky < 5 && kx < 5) {
            int src = co * 25 + ky * 5 + kx;
            w = scinol_p(w0[src], wS2[src], wG[src], weta[src], M, wG[src] != 0.0f);
        }
        g_w1h[p] = __float2half(w);
    }
    if (tid < 64)
        g_b1[tid] = scinol_p(b0[tid], bS2[tid], bG[tid], beta[tid], 1.0f, bG[tid] != 0.0f);
}

// ---------------------------------------------------------------------------
// Conv1 via fp16 HMMA single-product (R15-proven). Also resets ctr1/ctr_lin
// for the next graph replay.
// ---------------------------------------------------------------------------
__global__ void __launch_bounds__(256, 2) k_conv1(const float* __restrict__ x) {
    __shared__ uint32_t imgw[2048];
    int tid = threadIdx.x;
    int wid = tid >> 5, lane = tid & 31;
    int n2 = blockIdx.x;

    if (n2 == 0 && tid == 0) { g_ctr1 = 0; g_ctr_lin = 0; }

    for (int i = tid; i < 2048; i += 256) imgw[i] = 0;
    __syncthreads();

    for (int i = tid; i < 1568; i += 256) {
        int s = (i >= 784) ? 1 : 0;
        int j = i - s * 784;
        int r = j / 28, w = j - r * 28;
        const float* xp = x + (size_t)(n2 * 2 + s) * 784 + r * 28;
        float v0 = xp[w];
        float v1 = (w + 1 < 28) ? xp[w + 1] : 0.0f;
        uint32_t hw = (uint32_t)__half_as_ushort(__float2half(v0)) |
                      ((uint32_t)__half_as_ushort(__float2half(v1)) << 16);
        imgw[s * 1024 + r * 32 + w] = hw;
    }

    int s = wid >> 2, cobase = (wid & 3) << 4;
    int r4 = lane >> 2, c4 = lane & 3;

    uint32_t awh[3][4];
    {
        const char* wh = (const char*)g_w1h;
        int r0 = cobase + r4, r8 = r0 + 8;
        #pragma unroll
        for (int ks = 0; ks < 3; ks++) {
            int kb = ks * 16 + c4 * 2;
            awh[ks][0] = *(const uint32_t*)(wh + (r0 * 48 + kb) * 2);
            awh[ks][1] = *(const uint32_t*)(wh + (r8 * 48 + kb) * 2);
            awh[ks][2] = *(const uint32_t*)(wh + (r0 * 48 + kb + 8) * 2);
            awh[ks][3] = *(const uint32_t*)(wh + (r8 * 48 + kb + 8) * 2);
        }
    }
    float bv0 = g_b1[cobase + r4];
    float bv1 = g_b1[cobase + r4 + 8];
    __syncthreads();

    uint32_t wt[3];
    #pragma unroll
    for (int sub = 0; sub < 3; sub++)
        wt[sub] = (uint32_t)(s * 1024 + sub * 8 + r4 + c4 * 2);

    float px0[3], px1[3];
    float chmax0 = 0.0f, chmax1 = 0.0f;
    size_t nsamp = (size_t)(n2 * 2 + s);

    for (int oy = 0; oy < 24; oy++) {
        #pragma unroll
        for (int sub = 0; sub < 3; sub++) {
            float acc[4] = {0.0f, 0.0f, 0.0f, 0.0f};
            #pragma unroll
            for (int ks = 0; ks < 3; ks++) {
                uint32_t ro = (uint32_t)(oy + 2 * ks) * 32;
                uint32_t bh[2];
                bh[0] = imgw[wt[sub] + ro];
                bh[1] = imgw[wt[sub] + ro + 32];
                mma16816h(acc, awh[ks], bh);
            }
            float p0 = fmaxf(acc[0], acc[1]);
            float p1 = fmaxf(acc[2], acc[3]);
            if ((oy & 1) == 0) {
                px0[sub] = p0; px1[sub] = p1;
            } else {
                float v0 = fmaxf(fmaxf(px0[sub], p0) + bv0, 0.0f);
                float v1 = fmaxf(fmaxf(px1[sub], p1) + bv1, 0.0f);
                chmax0 = fmaxf(chmax0, v0);
                chmax1 = fmaxf(chmax1, v1);
                int pp = (oy >> 1) * 12 + sub * 4 + c4;
                size_t idx = (nsamp * 144 + pp) * 64 + cobase + r4;
                g_p1h[idx]     = __float2half(v0);
                g_p1h[idx + 8] = __float2half(v1);
            }
        }
    }
    chmax0 = fmaxf(chmax0, __shfl_xor_sync(0xFFFFFFFFu, chmax0, 1));
    chmax0 = fmaxf(chmax0, __shfl_xor_sync(0xFFFFFFFFu, chmax0, 2));
    chmax1 = fmaxf(chmax1, __shfl_xor_sync(0xFFFFFFFFu, chmax1, 1));
    chmax1 = fmaxf(chmax1, __shfl_xor_sync(0xFFFFFFFFu, chmax1, 2));
    if (c4 == 0) {
        g_max2[(size_t)(cobase + r4) * 2048 + nsamp] = chmax0;
        g_max2[(size_t)(cobase + r4 + 8) * 2048 + nsamp] = chmax1;
    }
}

// ---------------------------------------------------------------------------
// k_w2 (fused): blocks 0-63 compute stat2[c] (coalesced row reduce), all 160
// blocks gate on counter, then build conv2 fp16 weights + bias.
// ---------------------------------------------------------------------------
__global__ void k_w2(const float* __restrict__ w0, const float* __restrict__ wS2,
                     const float* __restrict__ wG, const float* __restrict__ weta,
                     const float* __restrict__ wM,
                     const float* __restrict__ b0, const float* __restrict__ bS2,
                     const float* __restrict__ bG, const float* __restrict__ beta) {
    int b = blockIdx.x;
    int tid = threadIdx.x;

    if (b < 64) {
        const float* row = g_max2 + (size_t)b * 2048;
        float s = 0.0f;
        for (int i = tid; i < 2048; i += 256) s += row[i];
        __shared__ float sm[8];
        s = warp_sum(s);
        if ((tid & 31) == 0) sm[tid >> 5] = s;
        __syncthreads();
        if (tid < 32) {
            float v = (tid < 8) ? sm[tid] : 0.0f;
            v = warp_sum(v);
            if (tid == 0) {
                g_stat2[b] = v * (1.0f / 2048.0f);
                __threadfence();
                atomicAdd(&g_ctr_w2, 1);
            }
        }
    }

    if (tid == 0) spin_until(&g_ctr_w2, 64);
    __syncthreads();

    int tot = gridDim.x * blockDim.x;
    int gid = b * blockDim.x + tid;
    for (int p = gid; p < 102400; p += tot) {
        int ci = p & 63;
        int co = (p >> 6) & 63;
        int pos = p >> 12;
        float M = fmaxf(g_stat2[ci], wM[ci]);
        int src = (co * 64 + ci) * 25 + pos;
        float w = scinol_p(w0[src], wS2[src], wG[src], weta[src], M, wG[src] != 0.0f);
        g_w2h[p] = __float2half(w);
    }
    for (int i = gid; i < 64; i += tot)
        g_b2[i] = scinol_p(b0[i], bS2[i], bG[i], beta[i], 1.0f, bG[i] != 0.0f);
}

// ---------------------------------------------------------------------------
// Conv2 via mma.sync pure fp16 single-product implicit GEMM (R14-proven).
// Also resets ctr_w2 for the next graph replay.
// Smem: winH 41472 + BH 9216 = 50688 B, 2 CTAs/SM.
// ---------------------------------------------------------------------------
__global__ void __launch_bounds__(256, 2) k_conv2() {
    extern __shared__ char smc[];
    char* winH = smc;
    char* BH   = smc + 41472;

    int tid = threadIdx.x;
    int wid = tid >> 5, lane = tid & 31;
    int n2 = blockIdx.x;
    int wm = wid & 3, wn = wid >> 2;
    int r4 = lane >> 2, c4 = lane & 3;

    if (n2 == 0 && tid == 0) g_ctr_w2 = 0;

    {
        const uint2* sh = (const uint2*)g_p1h + (size_t)n2 * 288 * 16;
        for (int i = tid; i < 4608; i += 256) {
            int row = i >> 4, c8 = i & 15;
            uint32_t off = (uint32_t)row * 144 + c8 * 8;
            *(uint2*)(winH + off) = sh[i];
        }
    }

    float acc[2][4][4];
    #pragma unroll
    for (int t = 0; t < 2; t++)
        #pragma unroll
        for (int nt = 0; nt < 4; nt++)
            #pragma unroll
            for (int e = 0; e < 4; e++) acc[t][nt][e] = 0.0f;

    uint32_t brow[4];
    #pragma unroll
    for (int nt = 0; nt < 4; nt++) brow[nt] = (uint32_t)(wn * 32 + nt * 8 + r4) * 144;

    uint32_t abase[2][2];
    #pragma unroll
    for (int t = 0; t < 2; t++) {
        int m = wm * 32 + t * 16 + r4;
        int s_ = m >> 6, oy = (m >> 3) & 7, ox = m & 7;
        int pix = s_ * 144 + oy * 12 + ox;
        abase[t][0] = (uint32_t)pix * 144;
        abase[t][1] = (uint32_t)(pix + 12) * 144;
    }

    const uint2* w2h2 = (const uint2*)g_w2h;

    for (int pos = 0; pos < 25; pos++) {
        int ky = pos / 5, kx = pos - ky * 5;
        uint32_t pdelta = (uint32_t)(ky * 12 + kx) * 144;

        __syncthreads();
        {
            size_t base = (size_t)pos * 1024;
            #pragma unroll
            for (int j = 0; j < 2; j++) {
                int i = tid + j * 256;
                int row = i >> 3, c8 = i & 7;
                uint32_t off = (uint32_t)row * 144 + c8 * 16;
                *(uint2*)(BH + off) = w2h2[base + i * 2];
                *(uint2*)(BH + off + 8) = w2h2[base + i * 2 + 1];
            }
        }
        __syncthreads();

        uint32_t arow[2][2];
        #pragma unroll
        for (int t = 0; t < 2; t++) {
            arow[t][0] = abase[t][0] + pdelta;
            arow[t][1] = abase[t][1] + pdelta;
        }

        #pragma unroll
        for (int ks = 0; ks < 4; ks++) {
            uint32_t kb = (uint32_t)(ks * 32 + c4 * 4);
            uint32_t ah[2][4], bh[4][2];
            #pragma unroll
            for (int t = 0; t < 2; t++) {
                ah[t][0] = *(const uint32_t*)(winH + arow[t][0] + kb);
                ah[t][1] = *(const uint32_t*)(winH + arow[t][1] + kb);
                ah[t][2] = *(const uint32_t*)(winH + arow[t][0] + kb + 16);
                ah[t][3] = *(const uint32_t*)(winH + arow[t][1] + kb + 16);
            }
            #pragma unroll
            for (int nt = 0; nt < 4; nt++) {
                bh[nt][0] = *(const uint32_t*)(BH + brow[nt] + kb);
                bh[nt][1] = *(const uint32_t*)(BH + brow[nt] + kb + 16);
            }
            #pragma unroll
            for (int t = 0; t < 2; t++)
                #pragma unroll
                for (int nt = 0; nt < 4; nt++)
                    mma16816h(acc[t][nt], ah[t], bh[nt]);
        }
    }

    int m0 = wm * 32 + r4;
    bool act = (r4 & 1) == 0;
    #pragma unroll
    for (int t = 0; t < 2; t++) {
        int m = m0 + t * 16;
        int s_ = m >> 6;
        int py = (m >> 4) & 3;
        int px = (r4 >> 1) & 3;
        float* outp = g_pool2 + (size_t)(n2 * 2 + s_) * 1024 + py * 4 + px;
        #pragma unroll
        for (int nt = 0; nt < 4; nt++) {
            float p0 = fmaxf(acc[t][nt][0], acc[t][nt][2]);
            float p1 = fmaxf(acc[t][nt][1], acc[t][nt][3]);
            float q0 = fmaxf(p0, __shfl_xor_sync(0xFFFFFFFFu, p0, 4));
            float q1 = fmaxf(p1, __shfl_xor_sync(0xFFFFFFFFu, p1, 4));
            if (act) {
                int co = wn * 32 + nt * 8 + c4 * 2;
                outp[co * 16]       = fmaxf(q0 + __ldg(g_b2 + co), 0.0f);
                outp[(co + 1) * 16] = fmaxf(q1 + __ldg(g_b2 + co + 1), 0.0f);
            }
        }
    }
}

// ---------------------------------------------------------------------------
// k_linear (fused): blocks 0-31 compute stat3 + linear weights (+ bias),
// all 2048 blocks gate on counter, then compute the output GEMV.
// 320 threads: stat phase uses 10 stripes x 32 features.
// ---------------------------------------------------------------------------
__global__ void __launch_bounds__(320) k_linear(
        const float* __restrict__ w0, const float* __restrict__ wS2,
        const float* __restrict__ wG, const float* __restrict__ weta,
        const float* __restrict__ wM,
        const float* __restrict__ b0, const float* __restrict__ bS2,
        const float* __restrict__ bG, const float* __restrict__ beta,
        float* __restrict__ out) {
    int tid = threadIdx.x;
    int blk = blockIdx.x;

    if (blk < 32) {
        __shared__ float sm2[10][32];
        __shared__ float sf[32];
        int fl = tid & 31, stripe = tid >> 5;   // stripe 0..9
        int f = blk * 32 + fl;
        float s = 0.0f;
        for (int n = stripe; n < 2048; n += 10)
            s += g_pool2[(size_t)n * 1024 + f];
        sm2[stripe][fl] = s;
        __syncthreads();
        if (stripe == 0) {
            float t = 0.0f;
            #pragma unroll
            for (int r = 0; r < 10; r++) t += sm2[r][fl];
            sf[fl] = t * (1.0f / 2048.0f);
        }
        __syncthreads();
        // 320 weights: o = tid>>5 (0..9), feature fl
        int gi = (tid >> 5) * 1024 + blk * 32 + fl;
        float M = fmaxf(wM[gi], sf[fl]);
        g_w3[gi] = scinol_p(w0[gi], wS2[gi], wG[gi], weta[gi], M, wS2[gi] != 0.0f);
        if (blk == 0 && tid < 10)
            g_b3[tid] = scinol_p(b0[tid], bS2[tid], bG[tid], beta[tid], 1.0f, bS2[tid] != 0.0f);
        __threadfence();
        __syncthreads();
        if (tid == 0) atomicAdd(&g_ctr_lin, 1);
    }

    if (tid == 0) spin_until(&g_ctr_lin, 32);
    __syncthreads();

    __shared__ float hs[1024];
    int n = blk;
    const float* src = g_pool2 + (size_t)n * 1024;
    for (int i = tid; i < 1024; i += 320) hs[i] = src[i];
    __syncthreads();
    int w = tid >> 5, lane = tid & 31;
    const float* wr = g_w3 + w * 1024;
    float s = 0.0f;
    #pragma unroll 8
    for (int k = lane; k < 1024; k += 32) s = fmaf(hs[k], wr[k], s);
    s = warp_sum(s);
    if (lane == 0) out[n * 10 + w] = s + g_b3[w];
}

// ---------------------------------------------------------------------------
// Launch
// ---------------------------------------------------------------------------
extern "C" void kernel_launch(void* const* d_in, const int* in_sizes, int n_in,
                              void* d_out, int out_size) {
    const float* x = (const float*)d_in[0];
    const float* c1_w0 = (const float*)d_in[1];
    const float* c1_wS2 = (const float*)d_in[2];
    const float* c1_wG = (const float*)d_in[3];
    const float* c1_weta = (const float*)d_in[4];
    const float* c1_wM = (const float*)d_in[5];
    const float* c1_b0 = (const float*)d_in[6];
    const float* c1_bS2 = (const float*)d_in[7];
    const float* c1_bG = (const float*)d_in[8];
    const float* c1_beta = (const float*)d_in[9];
    const float* c2_w0 = (const float*)d_in[10];
    const float* c2_wS2 = (const float*)d_in[11];
    const float* c2_wG = (const float*)d_in[12];
    const float* c2_weta = (const float*)d_in[13];
    const float* c2_wM = (const float*)d_in[14];
    const float* c2_b0 = (const float*)d_in[15];
    const float* c2_bS2 = (const float*)d_in[16];
    const float* c2_bG = (const float*)d_in[17];
    const float* c2_beta = (const float*)d_in[18];
    const float* l_w0 = (const float*)d_in[19];
    const float* l_wS2 = (const float*)d_in[20];
    const float* l_wG = (const float*)d_in[21];
    const float* l_weta = (const float*)d_in[22];
    const float* l_wM = (const float*)d_in[23];
    const float* l_b0 = (const float*)d_in[24];
    const float* l_bS2 = (const float*)d_in[25];
    const float* l_bG = (const float*)d_in[26];
    const float* l_beta = (const float*)d_in[27];
    float* out = (float*)d_out;

    cudaFuncSetAttribute(k_conv2, cudaFuncAttributeMaxDynamicSharedMemorySize, 50688);

    k_stat1<<<2048, 256>>>(x, c1_w0, c1_wS2, c1_wG, c1_weta, c1_wM,
                           c1_b0, c1_bS2, c1_bG, c1_beta);
    k_conv1<<<1024, 256>>>(x);
    k_w2<<<160, 256>>>(c2_w0, c2_wS2, c2_wG, c2_weta, c2_wM, c2_b0, c2_bS2, c2_bG, c2_beta);
    k_conv2<<<1024, 256, 50688>>>();
    k_linear<<<2048, 320>>>(l_w0, l_wS2, l_wG, l_weta, l_wM,
                            l_b0, l_bS2, l_bG, l_beta, out);
}

// round 17
// speedup vs baseline: 1.0632x; 1.0632x over previous
#include <cuda_runtime.h>
#include <cuda_fp16.h>
#include <math.h>
#include <stdint.h>

// ---------------------------------------------------------------------------
// Scratch (device globals — no allocation allowed)
// ---------------------------------------------------------------------------
__device__ __half         g_w1h[64 * 48];      // conv1 weights fp16 [co][k=ky*8+kx]
__device__ float          g_b1[64];
__device__ __half         g_w2h[25 * 64 * 64]; // conv2 weights fp16 [pos][co][ci]
__device__ float          g_b2[64];
__device__ float          g_w3[10 * 1024];
__device__ float          g_b3[10];
__device__ __half         g_p1h[(size_t)2048 * 144 * 64];  // pool1 fp16, ch-last
__device__ float          g_pool2[(size_t)2048 * 1024];
__device__ float          g_smax1[2048];
__device__ float          g_max2[64 * 2048];   // transposed: [c][n]
__device__ float          g_stat2[64];
__device__ int            g_ctr1;              // stat1 arrivals   (reset by k_conv1)
__device__ int            g_ctr_w2;            // stat2 arrivals   (reset by k_conv2)
__device__ int            g_ctr_lin;           // stat3 arrivals   (reset by k_conv1)

// ---------------------------------------------------------------------------
// Helpers
// ---------------------------------------------------------------------------
__device__ __forceinline__ float warp_max(float v) {
    #pragma unroll
    for (int o = 16; o; o >>= 1) v = fmaxf(v, __shfl_xor_sync(0xFFFFFFFFu, v, o));
    return v;
}
__device__ __forceinline__ float warp_sum(float v) {
    #pragma unroll
    for (int o = 16; o; o >>= 1) v += __shfl_xor_sync(0xFFFFFFFFu, v, o);
    return v;
}
__device__ __forceinline__ float scinol_p(float p0, float S2, float G, float eta,
                                          float M, bool cond) {
    float denom = sqrtf(S2 + M * M);
    float theta = fminf(fmaxf(G / denom, -1.0f), 1.0f);
    float upd = cond ? theta / (2.0f * denom) * eta : 0.0f;
    return p0 + upd;
}

// fp16 HMMA: D(16x8) += A(16x16)*B(16x8), fp32 accum. sm_80+.
__device__ __forceinline__ void mma16816h(float* d, const uint32_t* a, const uint32_t* b) {
    asm volatile(
        "mma.sync.aligned.m16n8k16.row.col.f32.f16.f16.f32 "
        "{%0,%1,%2,%3}, {%4,%5,%6,%7}, {%8,%9}, {%0,%1,%2,%3};"
        : "+f"(d[0]), "+f"(d[1]), "+f"(d[2]), "+f"(d[3])
        : "r"(a[0]), "r"(a[1]), "r"(a[2]), "r"(a[3]), "r"(b[0]), "r"(b[1]));
}

// ldmatrix x4 (sm_75+)
__device__ __forceinline__ void ldsm_x4(uint32_t* r, uint32_t saddr) {
    asm volatile("ldmatrix.sync.aligned.m8n8.x4.shared.b16 {%0,%1,%2,%3}, [%4];"
                 : "=r"(r[0]), "=r"(r[1]), "=r"(r[2]), "=r"(r[3]) : "r"(saddr));
}

__device__ __forceinline__ void spin_until(int* ctr, int target) {
    while (*(volatile int*)ctr < target) { }
    __threadfence();
}

// ---------------------------------------------------------------------------
// k_stat1 (fused): per-sample max of |x|; last block finalizes mean and
// builds conv1 weights (fp16, [co][48]) + bias.
// ---------------------------------------------------------------------------
__global__ void k_stat1(const float* __restrict__ x,
                        const float* __restrict__ w0, const float* __restrict__ wS2,
                        const float* __restrict__ wG, const float* __restrict__ weta,
                        const float* __restrict__ wM,
                        const float* __restrict__ b0, const float* __restrict__ bS2,
                        const float* __restrict__ bG, const float* __restrict__ beta) {
    int n = blockIdx.x;
    int tid = threadIdx.x;
    const float* xp = x + (size_t)n * 784;
    float m = 0.0f;
    for (int i = tid; i < 784; i += 256) m = fmaxf(m, fabsf(xp[i]));
    __shared__ float s[8];
    __shared__ int sold;
    m = warp_max(m);
    if ((tid & 31) == 0) s[tid >> 5] = m;
    __syncthreads();
    if (tid < 32) {
        float v = (tid < 8) ? s[tid] : 0.0f;
        v = warp_max(v);
        if (tid == 0) {
            g_smax1[n] = v;
            __threadfence();
            sold = atomicAdd(&g_ctr1, 1);
        }
    }
    __syncthreads();
    if (sold != 2047) return;

    __threadfence();
    __shared__ float sm[8];
    __shared__ float s_stat;
    float sum = 0.0f;
    for (int i = tid; i < 2048; i += 256) sum += g_smax1[i];
    sum = warp_sum(sum);
    if ((tid & 31) == 0) sm[tid >> 5] = sum;
    __syncthreads();
    if (tid < 32) {
        float v = (tid < 8) ? sm[tid] : 0.0f;
        v = warp_sum(v);
        if (tid == 0) s_stat = v * (1.0f / 2048.0f);
    }
    __syncthreads();
    float M = fmaxf(s_stat, wM[0]);

    for (int p = tid; p < 3072; p += 256) {
        int co = p / 48, k = p - co * 48;
        int ky = k >> 3, kx = k & 7;
        float w = 0.0f;
        if (ky < 5 && kx < 5) {
            int src = co * 25 + ky * 5 + kx;
            w = scinol_p(w0[src], wS2[src], wG[src], weta[src], M, wG[src] != 0.0f);
        }
        g_w1h[p] = __float2half(w);
    }
    if (tid < 64)
        g_b1[tid] = scinol_p(b0[tid], bS2[tid], bG[tid], beta[tid], 1.0f, bG[tid] != 0.0f);
}

// ---------------------------------------------------------------------------
// Conv1 via fp16 HMMA single-product (R15-proven). Resets ctr1/ctr_lin.
// ---------------------------------------------------------------------------
__global__ void __launch_bounds__(256, 2) k_conv1(const float* __restrict__ x) {
    __shared__ uint32_t imgw[2048];
    int tid = threadIdx.x;
    int wid = tid >> 5, lane = tid & 31;
    int n2 = blockIdx.x;

    if (n2 == 0 && tid == 0) { g_ctr1 = 0; g_ctr_lin = 0; }

    for (int i = tid; i < 2048; i += 256) imgw[i] = 0;
    __syncthreads();

    for (int i = tid; i < 1568; i += 256) {
        int s = (i >= 784) ? 1 : 0;
        int j = i - s * 784;
        int r = j / 28, w = j - r * 28;
        const float* xp = x + (size_t)(n2 * 2 + s) * 784 + r * 28;
        float v0 = xp[w];
        float v1 = (w + 1 < 28) ? xp[w + 1] : 0.0f;
        uint32_t hw = (uint32_t)__half_as_ushort(__float2half(v0)) |
                      ((uint32_t)__half_as_ushort(__float2half(v1)) << 16);
        imgw[s * 1024 + r * 32 + w] = hw;
    }

    int s = wid >> 2, cobase = (wid & 3) << 4;
    int r4 = lane >> 2, c4 = lane & 3;

    uint32_t awh[3][4];
    {
        const char* wh = (const char*)g_w1h;
        int r0 = cobase + r4, r8 = r0 + 8;
        #pragma unroll
        for (int ks = 0; ks < 3; ks++) {
            int kb = ks * 16 + c4 * 2;
            awh[ks][0] = *(const uint32_t*)(wh + (r0 * 48 + kb) * 2);
            awh[ks][1] = *(const uint32_t*)(wh + (r8 * 48 + kb) * 2);
            awh[ks][2] = *(const uint32_t*)(wh + (r0 * 48 + kb + 8) * 2);
            awh[ks][3] = *(const uint32_t*)(wh + (r8 * 48 + kb + 8) * 2);
        }
    }
    float bv0 = g_b1[cobase + r4];
    float bv1 = g_b1[cobase + r4 + 8];
    __syncthreads();

    uint32_t wt[3];
    #pragma unroll
    for (int sub = 0; sub < 3; sub++)
        wt[sub] = (uint32_t)(s * 1024 + sub * 8 + r4 + c4 * 2);

    float px0[3], px1[3];
    float chmax0 = 0.0f, chmax1 = 0.0f;
    size_t nsamp = (size_t)(n2 * 2 + s);

    for (int oy = 0; oy < 24; oy++) {
        #pragma unroll
        for (int sub = 0; sub < 3; sub++) {
            float acc[4] = {0.0f, 0.0f, 0.0f, 0.0f};
            #pragma unroll
            for (int ks = 0; ks < 3; ks++) {
                uint32_t ro = (uint32_t)(oy + 2 * ks) * 32;
                uint32_t bh[2];
                bh[0] = imgw[wt[sub] + ro];
                bh[1] = imgw[wt[sub] + ro + 32];
                mma16816h(acc, awh[ks], bh);
            }
            float p0 = fmaxf(acc[0], acc[1]);
            float p1 = fmaxf(acc[2], acc[3]);
            if ((oy & 1) == 0) {
                px0[sub] = p0; px1[sub] = p1;
            } else {
                float v0 = fmaxf(fmaxf(px0[sub], p0) + bv0, 0.0f);
                float v1 = fmaxf(fmaxf(px1[sub], p1) + bv1, 0.0f);
                chmax0 = fmaxf(chmax0, v0);
                chmax1 = fmaxf(chmax1, v1);
                int pp = (oy >> 1) * 12 + sub * 4 + c4;
                size_t idx = (nsamp * 144 + pp) * 64 + cobase + r4;
                g_p1h[idx]     = __float2half(v0);
                g_p1h[idx + 8] = __float2half(v1);
            }
        }
    }
    chmax0 = fmaxf(chmax0, __shfl_xor_sync(0xFFFFFFFFu, chmax0, 1));
    chmax0 = fmaxf(chmax0, __shfl_xor_sync(0xFFFFFFFFu, chmax0, 2));
    chmax1 = fmaxf(chmax1, __shfl_xor_sync(0xFFFFFFFFu, chmax1, 1));
    chmax1 = fmaxf(chmax1, __shfl_xor_sync(0xFFFFFFFFu, chmax1, 2));
    if (c4 == 0) {
        g_max2[(size_t)(cobase + r4) * 2048 + nsamp] = chmax0;
        g_max2[(size_t)(cobase + r4 + 8) * 2048 + nsamp] = chmax1;
    }
}

// ---------------------------------------------------------------------------
// k_w2 (fused): blocks 0-63 compute stat2[c], all gate, then build weights.
// ---------------------------------------------------------------------------
__global__ void k_w2(const float* __restrict__ w0, const float* __restrict__ wS2,
                     const float* __restrict__ wG, const float* __restrict__ weta,
                     const float* __restrict__ wM,
                     const float* __restrict__ b0, const float* __restrict__ bS2,
                     const float* __restrict__ bG, const float* __restrict__ beta) {
    int b = blockIdx.x;
    int tid = threadIdx.x;

    if (b < 64) {
        const float* row = g_max2 + (size_t)b * 2048;
        float s = 0.0f;
        for (int i = tid; i < 2048; i += 256) s += row[i];
        __shared__ float sm[8];
        s = warp_sum(s);
        if ((tid & 31) == 0) sm[tid >> 5] = s;
        __syncthreads();
        if (tid < 32) {
            float v = (tid < 8) ? sm[tid] : 0.0f;
            v = warp_sum(v);
            if (tid == 0) {
                g_stat2[b] = v * (1.0f / 2048.0f);
                __threadfence();
                atomicAdd(&g_ctr_w2, 1);
            }
        }
    }

    if (tid == 0) spin_until(&g_ctr_w2, 64);
    __syncthreads();

    int tot = gridDim.x * blockDim.x;
    int gid = b * blockDim.x + tid;
    for (int p = gid; p < 102400; p += tot) {
        int ci = p & 63;
        int co = (p >> 6) & 63;
        int pos = p >> 12;
        float M = fmaxf(g_stat2[ci], wM[ci]);
        int src = (co * 64 + ci) * 25 + pos;
        float w = scinol_p(w0[src], wS2[src], wG[src], weta[src], M, wG[src] != 0.0f);
        g_w2h[p] = __float2half(w);
    }
    for (int i = gid; i < 64; i += tot)
        g_b2[i] = scinol_p(b0[i], bS2[i], bG[i], beta[i], 1.0f, bG[i] != 0.0f);
}

// ---------------------------------------------------------------------------
// Conv2 via mma.sync fp16 + ldmatrix fragment loads, 3 CTAs/SM.
// Smem: winH 41472 + BH 9216 = 50688 B.
// ---------------------------------------------------------------------------
__global__ void __launch_bounds__(256, 3) k_conv2() {
    extern __shared__ char smc[];
    char* winH = smc;
    char* BH   = smc + 41472;

    int tid = threadIdx.x;
    int wid = tid >> 5, lane = tid & 31;
    int n2 = blockIdx.x;
    int wm = wid & 3, wn = wid >> 2;

    if (n2 == 0 && tid == 0) g_ctr_w2 = 0;

    {
        const uint2* sh = (const uint2*)g_p1h + (size_t)n2 * 288 * 16;
        for (int i = tid; i < 4608; i += 256) {
            int row = i >> 4, c8 = i & 15;
            uint32_t off = (uint32_t)row * 144 + c8 * 8;
            *(uint2*)(winH + off) = sh[i];
        }
    }

    float acc[2][4][4];
    #pragma unroll
    for (int t = 0; t < 2; t++)
        #pragma unroll
        for (int nt = 0; nt < 4; nt++)
            #pragma unroll
            for (int e = 0; e < 4; e++) acc[t][nt][e] = 0.0f;

    uint32_t winS = (uint32_t)__cvta_generic_to_shared(winH);
    uint32_t bhS  = (uint32_t)__cvta_generic_to_shared(BH);

    // ldmatrix per-lane base offsets
    int g = lane & 7, grp = lane >> 3;
    uint32_t aoffb[2];
    #pragma unroll
    for (int t = 0; t < 2; t++) {
        int rr = g + ((grp & 1) << 3);          // row within 16-row tile
        int m = wm * 32 + t * 16 + rr;
        int pix = (m >> 6) * 144 + ((m >> 3) & 7) * 12 + (m & 7);
        aoffb[t] = (uint32_t)pix * 144 + ((uint32_t)(grp >> 1) << 4);
    }
    uint32_t boffb[2];
    #pragma unroll
    for (int p = 0; p < 2; p++) {
        int n = wn * 32 + p * 16 + ((grp >> 1) << 3) + g;
        boffb[p] = bhS + (uint32_t)n * 144 + ((uint32_t)(grp & 1) << 4);
    }

    const uint2* w2h2 = (const uint2*)g_w2h;

    for (int pos = 0; pos < 25; pos++) {
        int ky = pos / 5, kx = pos - ky * 5;
        uint32_t pdelta = (uint32_t)(ky * 12 + kx) * 144;

        __syncthreads();
        {   // stage B tile (fp16): 512 x 8B chunks
            size_t base = (size_t)pos * 1024;
            #pragma unroll
            for (int j = 0; j < 2; j++) {
                int i = tid + j * 256;
                int row = i >> 3, c8 = i & 7;
                uint32_t off = (uint32_t)row * 144 + c8 * 16;
                *(uint2*)(BH + off) = w2h2[base + i * 2];
                *(uint2*)(BH + off + 8) = w2h2[base + i * 2 + 1];
            }
        }
        __syncthreads();

        uint32_t aA0 = winS + aoffb[0] + pdelta;
        uint32_t aA1 = winS + aoffb[1] + pdelta;

        #pragma unroll
        for (int ks = 0; ks < 4; ks++) {
            uint32_t ko = (uint32_t)ks * 32;
            uint32_t a0[4], a1[4], b0[4], b1[4];
            ldsm_x4(a0, aA0 + ko);
            ldsm_x4(a1, aA1 + ko);
            ldsm_x4(b0, boffb[0] + ko);
            ldsm_x4(b1, boffb[1] + ko);
            mma16816h(acc[0][0], a0, b0);
            mma16816h(acc[0][1], a0, b0 + 2);
            mma16816h(acc[0][2], a0, b1);
            mma16816h(acc[0][3], a0, b1 + 2);
            mma16816h(acc[1][0], a1, b0);
            mma16816h(acc[1][1], a1, b0 + 2);
            mma16816h(acc[1][2], a1, b1);
            mma16816h(acc[1][3], a1, b1 + 2);
        }
    }

    int r4 = lane >> 2, c4 = lane & 3;
    int m0 = wm * 32 + r4;
    bool act = (r4 & 1) == 0;
    #pragma unroll
    for (int t = 0; t < 2; t++) {
        int m = m0 + t * 16;
        int s_ = m >> 6;
        int py = (m >> 4) & 3;
        int px = (r4 >> 1) & 3;
        float* outp = g_pool2 + (size_t)(n2 * 2 + s_) * 1024 + py * 4 + px;
        #pragma unroll
        for (int nt = 0; nt < 4; nt++) {
            float p0 = fmaxf(acc[t][nt][0], acc[t][nt][2]);
            float p1 = fmaxf(acc[t][nt][1], acc[t][nt][3]);
            float q0 = fmaxf(p0, __shfl_xor_sync(0xFFFFFFFFu, p0, 4));
            float q1 = fmaxf(p1, __shfl_xor_sync(0xFFFFFFFFu, p1, 4));
            if (act) {
                int co = wn * 32 + nt * 8 + c4 * 2;
                outp[co * 16]       = fmaxf(q0 + __ldg(g_b2 + co), 0.0f);
                outp[(co + 1) * 16] = fmaxf(q1 + __ldg(g_b2 + co + 1), 0.0f);
            }
        }
    }
}

// ---------------------------------------------------------------------------
// k_linear (fused): blocks 0-31 compute stat3 + w3 (+ bias), all gate, GEMV.
// ---------------------------------------------------------------------------
__global__ void __launch_bounds__(320) k_linear(
        const float* __restrict__ w0, const float* __restrict__ wS2,
        const float* __restrict__ wG, const float* __restrict__ weta,
        const float* __restrict__ wM,
        const float* __restrict__ b0, const float* __restrict__ bS2,
        const float* __restrict__ bG, const float* __restrict__ beta,
        float* __restrict__ out) {
    int tid = threadIdx.x;
    int blk = blockIdx.x;

    if (blk < 32) {
        __shared__ float sm2[10][32];
        __shared__ float sf[32];
        int fl = tid & 31, stripe = tid >> 5;
        int f = blk * 32 + fl;
        float s = 0.0f;
        for (int n = stripe; n < 2048; n += 10)
            s += g_pool2[(size_t)n * 1024 + f];
        sm2[stripe][fl] = s;
        __syncthreads();
        if (stripe == 0) {
            float t = 0.0f;
            #pragma unroll
            for (int r = 0; r < 10; r++) t += sm2[r][fl];
            sf[fl] = t * (1.0f / 2048.0f);
        }
        __syncthreads();
        int gi = (tid >> 5) * 1024 + blk * 32 + fl;
        float M = fmaxf(wM[gi], sf[fl]);
        g_w3[gi] = scinol_p(w0[gi], wS2[gi], wG[gi], weta[gi], M, wS2[gi] != 0.0f);
        if (blk == 0 && tid < 10)
            g_b3[tid] = scinol_p(b0[tid], bS2[tid], bG[tid], beta[tid], 1.0f, bS2[tid] != 0.0f);
        __threadfence();
        __syncthreads();
        if (tid == 0) atomicAdd(&g_ctr_lin, 1);
    }

    if (tid == 0) spin_until(&g_ctr_lin, 32);
    __syncthreads();

    __shared__ float hs[1024];
    int n = blk;
    const float* src = g_pool2 + (size_t)n * 1024;
    for (int i = tid; i < 1024; i += 320) hs[i] = src[i];
    __syncthreads();
    int w = tid >> 5, lane = tid & 31;
    const float* wr = g_w3 + w * 1024;
    float s = 0.0f;
    #pragma unroll 8
    for (int k = lane; k < 1024; k += 32) s = fmaf(hs[k], wr[k], s);
    s = warp_sum(s);
    if (lane == 0) out[n * 10 + w] = s + g_b3[w];
}

// ---------------------------------------------------------------------------
// Launch
// ---------------------------------------------------------------------------
extern "C" void kernel_launch(void* const* d_in, const int* in_sizes, int n_in,
                              void* d_out, int out_size) {
    const float* x = (const float*)d_in[0];
    const float* c1_w0 = (const float*)d_in[1];
    const float* c1_wS2 = (const float*)d_in[2];
    const float* c1_wG = (const float*)d_in[3];
    const float* c1_weta = (const float*)d_in[4];
    const float* c1_wM = (const float*)d_in[5];
    const float* c1_b0 = (const float*)d_in[6];
    const float* c1_bS2 = (const float*)d_in[7];
    const float* c1_bG = (const float*)d_in[8];
    const float* c1_beta = (const float*)d_in[9];
    const float* c2_w0 = (const float*)d_in[10];
    const float* c2_wS2 = (const float*)d_in[11];
    const float* c2_wG = (const float*)d_in[12];
    const float* c2_weta = (const float*)d_in[13];
    const float* c2_wM = (const float*)d_in[14];
    const float* c2_b0 = (const float*)d_in[15];
    const float* c2_bS2 = (const float*)d_in[16];
    const float* c2_bG = (const float*)d_in[17];
    const float* c2_beta = (const float*)d_in[18];
    const float* l_w0 = (const float*)d_in[19];
    const float* l_wS2 = (const float*)d_in[20];
    const float* l_wG = (const float*)d_in[21];
    const float* l_weta = (const float*)d_in[22];
    const float* l_wM = (const float*)d_in[23];
    const float* l_b0 = (const float*)d_in[24];
    const float* l_bS2 = (const float*)d_in[25];
    const float* l_bG = (const float*)d_in[26];
    const float* l_beta = (const float*)d_in[27];
    float* out = (float*)d_out;

    cudaFuncSetAttribute(k_conv2, cudaFuncAttributeMaxDynamicSharedMemorySize, 50688);

    k_stat1<<<2048, 256>>>(x, c1_w0, c1_wS2, c1_wG, c1_weta, c1_wM,
                           c1_b0, c1_bS2, c1_bG, c1_beta);
    k_conv1<<<1024, 256>>>(x);
    k_w2<<<160, 256>>>(c2_w0, c2_wS2, c2_wG, c2_weta, c2_wM, c2_b0, c2_bS2, c2_bG, c2_beta);
    k_conv2<<<1024, 256, 50688>>>();
    k_linear<<<2048, 320>>>(l_w0, l_wS2, l_wG, l_weta, l_wM,
                            l_b0, l_bS2, l_bG, l_beta, out);
}